// round 8
// baseline (speedup 1.0000x reference)
#include <cuda_runtime.h>
#include <math.h>

#define N_STATIONS 100000
#define N_TIME     1000
#define K_NEIGH    8
#define SMOOTH_C   0.2f
#define KEEP_C     0.8f
#define N_COMP     4
#define COEFF_STRIDE 20   // 10 coeffs, duplicated {k,k} pairs = 5 float4
#define TABLE_STRIDE 12   // t, s0..s3, c0..c3, pad x3
#define CHUNKS     250    // 1000 times / 4 per thread
#define GRID_EVAL  592    // 148 SMs x 4 CTAs, one full wave
#define TILE       169    // stations per eval block (592*169 >= 100000)

// Scratch (no cudaMalloc allowed)
__device__ float g_coeff[N_STATIONS * COEFF_STRIDE];
__device__ float g_table[N_TIME * TABLE_STRIDE];
__device__ float g_trig [N_STATIONS * 8];   // per station: cos4, sin4

typedef unsigned long long u64;

// ---- packed f32x2 helpers ---------------------------------------------------
__device__ __forceinline__ u64 pk2(float lo, float hi) {
    u64 r; asm("mov.b64 %0, {%1, %2};" : "=l"(r) : "f"(lo), "f"(hi)); return r;
}
__device__ __forceinline__ u64 fma2(u64 a, u64 b, u64 c) {
    u64 d; asm("fma.rn.f32x2 %0, %1, %2, %3;" : "=l"(d) : "l"(a), "l"(b), "l"(c)); return d;
}
__device__ __forceinline__ u64 mul2(u64 a, u64 b) {
    u64 d; asm("mul.rn.f32x2 %0, %1, %2;" : "=l"(d) : "l"(a), "l"(b)); return d;
}
__device__ __forceinline__ u64 add2(u64 a, u64 b) {
    u64 d; asm("add.rn.f32x2 %0, %1, %2;" : "=l"(d) : "l"(a), "l"(b)); return d;
}
__device__ __forceinline__ void stcs2(void* p, u64 a, u64 b) {
    asm volatile("st.global.cs.v2.u64 [%0], {%1, %2};" :: "l"(p), "l"(a), "l"(b) : "memory");
}

// ---------------------------------------------------------------------------
// Kernel A: per-station trig table (accurate sincosf of every phase) + the
// time table (first N_TIME threads). All sincos happen ONCE here, fully
// parallel and not behind any gather.
// ---------------------------------------------------------------------------
__global__ void __launch_bounds__(256) trig_kernel(
    const float* __restrict__ phases,
    const float* __restrict__ time_vector,
    const float* __restrict__ periods)
{
    const int g = blockIdx.x * blockDim.x + threadIdx.x;

    if (g < N_TIME) {
        float t = time_vector[g];
        float e[TABLE_STRIDE];
        e[0] = t;
#pragma unroll
        for (int i = 0; i < N_COMP; ++i) {
            float w = 6.2831853071795864769f / periods[i];
            float sv, cv;
            sincosf(w * t, &sv, &cv);
            e[1 + i] = sv;
            e[5 + i] = cv;
        }
        e[9] = 0.f; e[10] = 0.f; e[11] = 0.f;
        float4* dst = reinterpret_cast<float4*>(g_table + g * TABLE_STRIDE);
        dst[0] = make_float4(e[0], e[1], e[2],  e[3]);
        dst[1] = make_float4(e[4], e[5], e[6],  e[7]);
        dst[2] = make_float4(e[8], e[9], e[10], e[11]);
    }

    if (g >= N_STATIONS) return;
    float4 p = *reinterpret_cast<const float4*>(phases + g * 4);
    float pv[4] = {p.x, p.y, p.z, p.w};
    float cv[4], sv[4];
#pragma unroll
    for (int i = 0; i < N_COMP; ++i)
        sincosf(pv[i], &sv[i], &cv[i]);
    float4* dst = reinterpret_cast<float4*>(g_trig + g * 8);
    dst[0] = make_float4(cv[0], cv[1], cv[2], cv[3]);
    dst[1] = make_float4(sv[0], sv[1], sv[2], sv[3]);
}

// ---------------------------------------------------------------------------
// Kernel B: smoothing — pure gather + FMA (zero MUFU behind gathers).
// Per station: 2 idx LDGs -> 24 independent gather LDG.128 -> FMA tree ->
// 4 rsqrt -> write duplicated coefficient pairs.
// ---------------------------------------------------------------------------
__global__ void __launch_bounds__(256) smooth_kernel(
    const float* __restrict__ off,
    const float* __restrict__ trend,
    const float* __restrict__ amps,
    const int*   __restrict__ nidx,
    const float* __restrict__ nw)
{
    const int st = blockIdx.x * blockDim.x + threadIdx.x;
    if (st >= N_STATIONS) return;

    int4   ni0 = __ldg(reinterpret_cast<const int4*>(nidx + st * K_NEIGH));
    int4   ni1 = __ldg(reinterpret_cast<const int4*>(nidx + st * K_NEIGH) + 1);
    float4 w0  = __ldg(reinterpret_cast<const float4*>(nw + st * K_NEIGH));
    float4 w1  = __ldg(reinterpret_cast<const float4*>(nw + st * K_NEIGH) + 1);
    int   nbv[K_NEIGH] = {ni0.x, ni0.y, ni0.z, ni0.w, ni1.x, ni1.y, ni1.z, ni1.w};
    float wv [K_NEIGH] = {w0.x,  w0.y,  w0.z,  w0.w,  w1.x,  w1.y,  w1.z,  w1.w};

    // front-batch all 24 gathers (independent; compiler hoists)
    float4 ga[K_NEIGH], gc[K_NEIGH], gs[K_NEIGH];
#pragma unroll
    for (int k = 0; k < K_NEIGH; ++k) {
        const int nb = nbv[k];
        ga[k] = __ldg(reinterpret_cast<const float4*>(amps  + (size_t)nb * 4));
        gc[k] = __ldg(reinterpret_cast<const float4*>(g_trig + (size_t)nb * 8));
        gs[k] = __ldg(reinterpret_cast<const float4*>(g_trig + (size_t)nb * 8) + 1);
    }
    float4 oa = __ldg(reinterpret_cast<const float4*>(amps  + (size_t)st * 4));
    float4 oc = __ldg(reinterpret_cast<const float4*>(g_trig + (size_t)st * 8));
    float4 os = __ldg(reinterpret_cast<const float4*>(g_trig + (size_t)st * 8) + 1);
    float  o  = __ldg(off + st);
    float  tr = __ldg(trend + st);

    float aa[N_COMP] = {0.f, 0.f, 0.f, 0.f};
    float re[N_COMP] = {0.f, 0.f, 0.f, 0.f};
    float im[N_COMP] = {0.f, 0.f, 0.f, 0.f};
#pragma unroll
    for (int k = 0; k < K_NEIGH; ++k) {
        float w = wv[k];
        float av[4] = {ga[k].x, ga[k].y, ga[k].z, ga[k].w};
        float cc[4] = {gc[k].x, gc[k].y, gc[k].z, gc[k].w};
        float ss[4] = {gs[k].x, gs[k].y, gs[k].z, gs[k].w};
#pragma unroll
        for (int i = 0; i < N_COMP; ++i) {
            aa[i] = fmaf(w, av[i], aa[i]);
            re[i] = fmaf(w, cc[i], re[i]);
            im[i] = fmaf(w, ss[i], im[i]);
        }
    }

    float a0[4] = {oa.x, oa.y, oa.z, oa.w};
    float c0[4] = {oc.x, oc.y, oc.z, oc.w};
    float s0[4] = {os.x, os.y, os.z, os.w};

    float A[N_COMP], B[N_COMP];
#pragma unroll
    for (int i = 0; i < N_COMP; ++i) {
        float amp_s = KEEP_C * a0[i] + SMOOTH_C * aa[i];
        float mr = KEEP_C * c0[i] + SMOOTH_C * re[i];
        float mi = KEEP_C * s0[i] + SMOOTH_C * im[i];
        float inv = rsqrtf(fmaxf(mr * mr + mi * mi, 1e-30f));
        A[i] = amp_s * mr * inv;
        B[i] = amp_s * mi * inv;
    }

    float4* dst = reinterpret_cast<float4*>(g_coeff + (size_t)st * COEFF_STRIDE);
    dst[0] = make_float4(o,    o,    tr,   tr);
    dst[1] = make_float4(A[0], A[0], A[1], A[1]);
    dst[2] = make_float4(A[2], A[2], A[3], A[3]);
    dst[3] = make_float4(B[0], B[0], B[1], B[1]);
    dst[4] = make_float4(B[2], B[2], B[3], B[3]);
}

// ---------------------------------------------------------------------------
// Kernel C: persistent evaluation (one full 4-CTA wave). Tile coefficients
// staged to smem once; broadcast LDS.128; table in regs; two FMA2 chains
// (depth 5 / 4) + 1 add2 = 10 ops per 4 outputs; streaming STG.128.
// ---------------------------------------------------------------------------
__global__ void __launch_bounds__(256, 4) eval_kernel(float* __restrict__ out)
{
    __shared__ float4 s_coeff[TILE * 5];   // 13520 B

    const int  col    = threadIdx.x;       // chunks 0..249 real
    const bool active = (col < CHUNKS);

    const int s_base = blockIdx.x * TILE;
    const int ns     = min(TILE, N_STATIONS - s_base);
    if (ns <= 0) return;

    {
        const float4* gsrc = reinterpret_cast<const float4*>(g_coeff) + (size_t)s_base * 5;
        const int total_f4 = ns * 5;
        for (int i = threadIdx.x; i < total_f4; i += 256)
            s_coeff[i] = gsrc[i];
    }

    u64 tt2[2];
    u64 ss2[2][4];
    u64 cc2[2][4];
    if (active) {
#pragma unroll
        for (int h = 0; h < 2; ++h) {
            const float* tpA = g_table + (col * 4 + 2 * h)     * TABLE_STRIDE;
            const float* tpB = g_table + (col * 4 + 2 * h + 1) * TABLE_STRIDE;
            float4 a0 = reinterpret_cast<const float4*>(tpA)[0];
            float4 a1 = reinterpret_cast<const float4*>(tpA)[1];
            float4 a2 = reinterpret_cast<const float4*>(tpA)[2];
            float4 b0 = reinterpret_cast<const float4*>(tpB)[0];
            float4 b1 = reinterpret_cast<const float4*>(tpB)[1];
            float4 b2 = reinterpret_cast<const float4*>(tpB)[2];
            tt2[h]    = pk2(a0.x, b0.x);
            ss2[h][0] = pk2(a0.y, b0.y);
            ss2[h][1] = pk2(a0.z, b0.z);
            ss2[h][2] = pk2(a0.w, b0.w);
            ss2[h][3] = pk2(a1.x, b1.x);
            cc2[h][0] = pk2(a1.y, b1.y);
            cc2[h][1] = pk2(a1.z, b1.z);
            cc2[h][2] = pk2(a1.w, b1.w);
            cc2[h][3] = pk2(a2.x, b2.x);
        }
    }

    __syncthreads();

    for (int j = 0; j < ns; ++j) {
        const ulonglong2* cp = reinterpret_cast<const ulonglong2*>(&s_coeff[j * 5]);
        ulonglong2 x0 = cp[0];  // {off,off},{trend,trend}
        ulonglong2 x1 = cp[1];  // {A0,A0},{A1,A1}
        ulonglong2 x2 = cp[2];  // {A2,A2},{A3,A3}
        ulonglong2 x3 = cp[3];  // {B0,B0},{B1,B1}
        ulonglong2 x4 = cp[4];  // {B2,B2},{B3,B3}

        if (active) {
            u64 r[2];
#pragma unroll
            for (int h = 0; h < 2; ++h) {
                u64 p0 = fma2(x0.y, tt2[h],    x0.x);    // off + trend*t
                u64 p1 = mul2(x3.x, cc2[h][0]);          // B0*c0
                p0 = fma2(x1.x, ss2[h][0], p0);          // +A0*s0
                p1 = fma2(x3.y, cc2[h][1], p1);          // +B1*c1
                p0 = fma2(x1.y, ss2[h][1], p0);          // +A1*s1
                p1 = fma2(x4.x, cc2[h][2], p1);          // +B2*c2
                p0 = fma2(x2.x, ss2[h][2], p0);          // +A2*s2
                p1 = fma2(x4.y, cc2[h][3], p1);          // +B3*c3
                p0 = fma2(x2.y, ss2[h][3], p0);          // +A3*s3
                r[h] = add2(p0, p1);
            }
            stcs2(out + (size_t)(s_base + j) * N_TIME + col * 4, r[0], r[1]);
        }
    }
}

// ---------------------------------------------------------------------------
extern "C" void kernel_launch(void* const* d_in, const int* in_sizes, int n_in,
                              void* d_out, int out_size)
{
    const float* time_vector = (const float*)d_in[0];
    const float* off         = (const float*)d_in[1];
    const float* trend       = (const float*)d_in[2];
    const float* amps        = (const float*)d_in[3];
    const float* phases      = (const float*)d_in[4];
    const int*   nidx        = (const int*)  d_in[5];
    const float* nw          = (const float*)d_in[6];
    const float* periods     = (const float*)d_in[7];
    float* out = (float*)d_out;

    trig_kernel  <<<(N_STATIONS + 255) / 256, 256>>>(phases, time_vector, periods);
    smooth_kernel<<<(N_STATIONS + 255) / 256, 256>>>(off, trend, amps, nidx, nw);
    eval_kernel  <<<GRID_EVAL, 256>>>(out);
}

// round 9
// speedup vs baseline: 1.0420x; 1.0420x over previous
#include <cuda_runtime.h>
#include <cuda_fp16.h>
#include <math.h>

#define N_STATIONS 100000
#define N_TIME     1000
#define K_NEIGH    8
#define SMOOTH_C   0.2f
#define KEEP_C     0.8f
#define N_COMP     4
#define COEFF_STRIDE 20   // 10 coeffs, duplicated {k,k} pairs = 5 float4
#define TABLE_STRIDE 12   // t, s0..s3, c0..c3, pad x3
#define CHUNKS     250    // 1000 times / 4 per thread
#define GRID_EVAL  592    // 148 SMs x 4 CTAs, one full wave
#define TILE       169    // stations per eval block (592*169 >= 100000)

// Scratch (no cudaMalloc allowed)
__device__ float  g_coeff[N_STATIONS * COEFF_STRIDE];
__device__ float  g_table[N_TIME * TABLE_STRIDE];
__device__ __half g_trig [N_STATIONS * 8];   // per station 16B: cos0..3, sin0..3

typedef unsigned long long u64;

// ---- packed f32x2 helpers ---------------------------------------------------
__device__ __forceinline__ u64 pk2(float lo, float hi) {
    u64 r; asm("mov.b64 %0, {%1, %2};" : "=l"(r) : "f"(lo), "f"(hi)); return r;
}
__device__ __forceinline__ u64 fma2(u64 a, u64 b, u64 c) {
    u64 d; asm("fma.rn.f32x2 %0, %1, %2, %3;" : "=l"(d) : "l"(a), "l"(b), "l"(c)); return d;
}
__device__ __forceinline__ u64 mul2(u64 a, u64 b) {
    u64 d; asm("mul.rn.f32x2 %0, %1, %2;" : "=l"(d) : "l"(a), "l"(b)); return d;
}
__device__ __forceinline__ u64 add2(u64 a, u64 b) {
    u64 d; asm("add.rn.f32x2 %0, %1, %2;" : "=l"(d) : "l"(a), "l"(b)); return d;
}
__device__ __forceinline__ void stcs2(void* p, u64 a, u64 b) {
    asm volatile("st.global.cs.v2.u64 [%0], {%1, %2};" :: "l"(p), "l"(a), "l"(b) : "memory");
}

// ---------------------------------------------------------------------------
// Kernel A: per-station fp16 phasor table via fast __sincosf (ONE 16B record
// per station -> one gather per neighbor later). First N_TIME threads also
// build the fp32 time table with accurate sincosf.
// ---------------------------------------------------------------------------
__global__ void __launch_bounds__(256) trig_kernel(
    const float* __restrict__ phases,
    const float* __restrict__ time_vector,
    const float* __restrict__ periods)
{
    const int g = blockIdx.x * blockDim.x + threadIdx.x;

    if (g < N_TIME) {
        float t = time_vector[g];
        float e[TABLE_STRIDE];
        e[0] = t;
#pragma unroll
        for (int i = 0; i < N_COMP; ++i) {
            float w = 6.2831853071795864769f / periods[i];
            float sv, cv;
            sincosf(w * t, &sv, &cv);   // accurate: eval path precision
            e[1 + i] = sv;
            e[5 + i] = cv;
        }
        e[9] = 0.f; e[10] = 0.f; e[11] = 0.f;
        float4* dst = reinterpret_cast<float4*>(g_table + g * TABLE_STRIDE);
        dst[0] = make_float4(e[0], e[1], e[2],  e[3]);
        dst[1] = make_float4(e[4], e[5], e[6],  e[7]);
        dst[2] = make_float4(e[8], e[9], e[10], e[11]);
    }

    if (g >= N_STATIONS) return;
    float4 p = *reinterpret_cast<const float4*>(phases + g * 4);
    float pv[4] = {p.x, p.y, p.z, p.w};
    float cv[4], sv[4];
#pragma unroll
    for (int i = 0; i < N_COMP; ++i)
        __sincosf(pv[i], &sv[i], &cv[i]);   // neighbor path: weight 0.2, fp16 anyway
    __half2 h[4];
    h[0] = __floats2half2_rn(cv[0], cv[1]);
    h[1] = __floats2half2_rn(cv[2], cv[3]);
    h[2] = __floats2half2_rn(sv[0], sv[1]);
    h[3] = __floats2half2_rn(sv[2], sv[3]);
    *reinterpret_cast<float4*>(g_trig + (size_t)g * 8) =
        *reinterpret_cast<float4*>(h);
}

// ---------------------------------------------------------------------------
// Kernel B: smoothing. TWO threads per station (even: nbrs 0-3, odd: 4-7).
// Per thread: 2 coalesced loads (idx4, w4) + 8 front-batched random gathers
// (amp fp32 16B + phasor fp16 16B per neighbor). shfl_xor(1) combines the
// halves; even lane finalizes components 0,1 / odd finalizes 2,3 with EXACT
// own-station __sincosf (weight 0.8 stays fp32-accurate).
// ---------------------------------------------------------------------------
__global__ void __launch_bounds__(256) smooth_kernel(
    const float* __restrict__ off,
    const float* __restrict__ trend,
    const float* __restrict__ amps,
    const float* __restrict__ phases,
    const int*   __restrict__ nidx,
    const float* __restrict__ nw)
{
    const int g    = blockIdx.x * blockDim.x + threadIdx.x;
    const int st   = g >> 1;
    const int half = g & 1;
    if (st >= N_STATIONS) return;

    int4   ni = __ldg(reinterpret_cast<const int4*>(nidx + st * K_NEIGH) + half);
    float4 wf = __ldg(reinterpret_cast<const float4*>(nw   + st * K_NEIGH) + half);
    int   nbv[4] = {ni.x, ni.y, ni.z, ni.w};
    float wv [4] = {wf.x, wf.y, wf.z, wf.w};

    // front-batch the 8 random gathers (fully independent)
    float4 ga[4], gt[4];
#pragma unroll
    for (int k = 0; k < 4; ++k) {
        const size_t nb = (size_t)nbv[k];
        ga[k] = __ldg(reinterpret_cast<const float4*>(amps + nb * 4));
        gt[k] = __ldg(reinterpret_cast<const float4*>(
                      reinterpret_cast<const char*>(g_trig) + nb * 16));
    }

    float aa[N_COMP] = {0.f, 0.f, 0.f, 0.f};
    float re[N_COMP] = {0.f, 0.f, 0.f, 0.f};
    float im[N_COMP] = {0.f, 0.f, 0.f, 0.f};
#pragma unroll
    for (int k = 0; k < 4; ++k) {
        float w = wv[k];
        const __half2* h = reinterpret_cast<const __half2*>(&gt[k]);
        float2 c01 = __half22float2(h[0]);
        float2 c23 = __half22float2(h[1]);
        float2 s01 = __half22float2(h[2]);
        float2 s23 = __half22float2(h[3]);
        float av[4] = {ga[k].x, ga[k].y, ga[k].z, ga[k].w};
        float cc[4] = {c01.x, c01.y, c23.x, c23.y};
        float ss[4] = {s01.x, s01.y, s23.x, s23.y};
#pragma unroll
        for (int i = 0; i < N_COMP; ++i) {
            aa[i] = fmaf(w, av[i], aa[i]);
            re[i] = fmaf(w, cc[i], re[i]);
            im[i] = fmaf(w, ss[i], im[i]);
        }
    }

    // combine halves (even/odd lanes of the same station share a warp)
    const unsigned m = 0xFFFFFFFFu;
#pragma unroll
    for (int i = 0; i < N_COMP; ++i) {
        aa[i] += __shfl_xor_sync(m, aa[i], 1);
        re[i] += __shfl_xor_sync(m, re[i], 1);
        im[i] += __shfl_xor_sync(m, im[i], 1);
    }

    // this lane finalizes components c0, c0+1 with exact own-station phasor
    const int c0 = half * 2;
    float2 oa = *reinterpret_cast<const float2*>(amps   + (size_t)st * 4 + c0);
    float2 op = *reinterpret_cast<const float2*>(phases + (size_t)st * 4 + c0);
    float a0[2] = {oa.x, oa.y};
    float p0[2] = {op.x, op.y};

    float A[2], B[2];
#pragma unroll
    for (int i = 0; i < 2; ++i) {
        float amp_s = KEEP_C * a0[i] + SMOOTH_C * aa[c0 + i];
        float sp, cp;
        __sincosf(p0[i], &sp, &cp);
        float mr = KEEP_C * cp + SMOOTH_C * re[c0 + i];
        float mi = KEEP_C * sp + SMOOTH_C * im[c0 + i];
        float inv = rsqrtf(fmaxf(mr * mr + mi * mi, 1e-30f));
        A[i] = amp_s * mr * inv;
        B[i] = amp_s * mi * inv;
    }

    float4* dst = reinterpret_cast<float4*>(g_coeff + (size_t)st * COEFF_STRIDE);
    if (half == 0) {
        float o  = __ldg(off + st);
        float tr = __ldg(trend + st);
        dst[0] = make_float4(o,    o,    tr,   tr);
        dst[1] = make_float4(A[0], A[0], A[1], A[1]);   // A0, A1
        dst[3] = make_float4(B[0], B[0], B[1], B[1]);   // B0, B1
    } else {
        dst[2] = make_float4(A[0], A[0], A[1], A[1]);   // A2, A3
        dst[4] = make_float4(B[0], B[0], B[1], B[1]);   // B2, B3
    }
}

// ---------------------------------------------------------------------------
// Kernel C: persistent evaluation (one full 4-CTA wave). Tile coefficients
// staged to smem once; broadcast LDS.128; table in regs; two FMA2 chains
// (depth 5 / 4) + 1 add2 = 10 ops per 4 outputs; streaming STG.128.
// ---------------------------------------------------------------------------
__global__ void __launch_bounds__(256, 4) eval_kernel(float* __restrict__ out)
{
    __shared__ float4 s_coeff[TILE * 5];   // 13520 B

    const int  col    = threadIdx.x;       // chunks 0..249 real
    const bool active = (col < CHUNKS);

    const int s_base = blockIdx.x * TILE;
    const int ns     = min(TILE, N_STATIONS - s_base);
    if (ns <= 0) return;

    {
        const float4* gsrc = reinterpret_cast<const float4*>(g_coeff) + (size_t)s_base * 5;
        const int total_f4 = ns * 5;
        for (int i = threadIdx.x; i < total_f4; i += 256)
            s_coeff[i] = gsrc[i];
    }

    u64 tt2[2];
    u64 ss2[2][4];
    u64 cc2[2][4];
    if (active) {
#pragma unroll
        for (int h = 0; h < 2; ++h) {
            const float* tpA = g_table + (col * 4 + 2 * h)     * TABLE_STRIDE;
            const float* tpB = g_table + (col * 4 + 2 * h + 1) * TABLE_STRIDE;
            float4 a0 = reinterpret_cast<const float4*>(tpA)[0];
            float4 a1 = reinterpret_cast<const float4*>(tpA)[1];
            float4 a2 = reinterpret_cast<const float4*>(tpA)[2];
            float4 b0 = reinterpret_cast<const float4*>(tpB)[0];
            float4 b1 = reinterpret_cast<const float4*>(tpB)[1];
            float4 b2 = reinterpret_cast<const float4*>(tpB)[2];
            tt2[h]    = pk2(a0.x, b0.x);
            ss2[h][0] = pk2(a0.y, b0.y);
            ss2[h][1] = pk2(a0.z, b0.z);
            ss2[h][2] = pk2(a0.w, b0.w);
            ss2[h][3] = pk2(a1.x, b1.x);
            cc2[h][0] = pk2(a1.y, b1.y);
            cc2[h][1] = pk2(a1.z, b1.z);
            cc2[h][2] = pk2(a1.w, b1.w);
            cc2[h][3] = pk2(a2.x, b2.x);
        }
    }

    __syncthreads();

    for (int j = 0; j < ns; ++j) {
        const ulonglong2* cp = reinterpret_cast<const ulonglong2*>(&s_coeff[j * 5]);
        ulonglong2 x0 = cp[0];  // {off,off},{trend,trend}
        ulonglong2 x1 = cp[1];  // {A0,A0},{A1,A1}
        ulonglong2 x2 = cp[2];  // {A2,A2},{A3,A3}
        ulonglong2 x3 = cp[3];  // {B0,B0},{B1,B1}
        ulonglong2 x4 = cp[4];  // {B2,B2},{B3,B3}

        if (active) {
            u64 r[2];
#pragma unroll
            for (int h = 0; h < 2; ++h) {
                u64 p0 = fma2(x0.y, tt2[h],    x0.x);    // off + trend*t
                u64 p1 = mul2(x3.x, cc2[h][0]);          // B0*c0
                p0 = fma2(x1.x, ss2[h][0], p0);          // +A0*s0
                p1 = fma2(x3.y, cc2[h][1], p1);          // +B1*c1
                p0 = fma2(x1.y, ss2[h][1], p0);          // +A1*s1
                p1 = fma2(x4.x, cc2[h][2], p1);          // +B2*c2
                p0 = fma2(x2.x, ss2[h][2], p0);          // +A2*s2
                p1 = fma2(x4.y, cc2[h][3], p1);          // +B3*c3
                p0 = fma2(x2.y, ss2[h][3], p0);          // +A3*s3
                r[h] = add2(p0, p1);
            }
            stcs2(out + (size_t)(s_base + j) * N_TIME + col * 4, r[0], r[1]);
        }
    }
}

// ---------------------------------------------------------------------------
extern "C" void kernel_launch(void* const* d_in, const int* in_sizes, int n_in,
                              void* d_out, int out_size)
{
    const float* time_vector = (const float*)d_in[0];
    const float* off         = (const float*)d_in[1];
    const float* trend       = (const float*)d_in[2];
    const float* amps        = (const float*)d_in[3];
    const float* phases      = (const float*)d_in[4];
    const int*   nidx        = (const int*)  d_in[5];
    const float* nw          = (const float*)d_in[6];
    const float* periods     = (const float*)d_in[7];
    float* out = (float*)d_out;

    trig_kernel  <<<(N_STATIONS + 255) / 256, 256>>>(phases, time_vector, periods);
    smooth_kernel<<<(2 * N_STATIONS + 255) / 256, 256>>>(off, trend, amps, phases, nidx, nw);
    eval_kernel  <<<GRID_EVAL, 256>>>(out);
}

// round 10
// speedup vs baseline: 1.0777x; 1.0343x over previous
#include <cuda_runtime.h>
#include <cuda_fp16.h>
#include <math.h>

#define N_STATIONS 100000
#define N_TIME     1000
#define K_NEIGH    8
#define SMOOTH_C   0.2f
#define KEEP_C     0.8f
#define N_COMP     4
#define COEFF_STRIDE 20   // 10 coeffs, duplicated {k,k} pairs = 5 float4
#define TABLE_STRIDE 12   // t, s0..s3, c0..c3, pad x3
#define CHUNKS     250    // 1000 times / 4 per thread
#define GRID_EVAL  592    // 148 SMs x 4 CTAs, one full wave
#define TILE       169    // stations per eval block (592*169 >= 100000)

// Scratch (no cudaMalloc allowed)
__device__ float  g_coeff[N_STATIONS * COEFF_STRIDE];
__device__ float  g_table[N_TIME * TABLE_STRIDE];
__device__ __half g_pack [N_STATIONS * 8];   // 16B/station: amp0..3, phase0..3 (fp16)

typedef unsigned long long u64;

// ---- packed f32x2 helpers ---------------------------------------------------
__device__ __forceinline__ u64 pk2(float lo, float hi) {
    u64 r; asm("mov.b64 %0, {%1, %2};" : "=l"(r) : "f"(lo), "f"(hi)); return r;
}
__device__ __forceinline__ u64 fma2(u64 a, u64 b, u64 c) {
    u64 d; asm("fma.rn.f32x2 %0, %1, %2, %3;" : "=l"(d) : "l"(a), "l"(b), "l"(c)); return d;
}
__device__ __forceinline__ u64 mul2(u64 a, u64 b) {
    u64 d; asm("mul.rn.f32x2 %0, %1, %2;" : "=l"(d) : "l"(a), "l"(b)); return d;
}
__device__ __forceinline__ u64 add2(u64 a, u64 b) {
    u64 d; asm("add.rn.f32x2 %0, %1, %2;" : "=l"(d) : "l"(a), "l"(b)); return d;
}
__device__ __forceinline__ void stcs2(void* p, u64 a, u64 b) {
    asm volatile("st.global.cs.v2.u64 [%0], {%1, %2};" :: "l"(p), "l"(a), "l"(b) : "memory");
}

// ---------------------------------------------------------------------------
// Kernel A: pack amps+phases into ONE fp16 16B record per station (so each
// neighbor later costs a single gather). First N_TIME threads also build the
// fp32 time table (accurate sincosf — eval precision path).
// ---------------------------------------------------------------------------
__global__ void __launch_bounds__(256) pack_kernel(
    const float* __restrict__ amps,
    const float* __restrict__ phases,
    const float* __restrict__ time_vector,
    const float* __restrict__ periods)
{
    const int g = blockIdx.x * blockDim.x + threadIdx.x;

    if (g < N_TIME) {
        float t = time_vector[g];
        float e[TABLE_STRIDE];
        e[0] = t;
#pragma unroll
        for (int i = 0; i < N_COMP; ++i) {
            float w = 6.2831853071795864769f / periods[i];
            float sv, cv;
            sincosf(w * t, &sv, &cv);
            e[1 + i] = sv;
            e[5 + i] = cv;
        }
        e[9] = 0.f; e[10] = 0.f; e[11] = 0.f;
        float4* dst = reinterpret_cast<float4*>(g_table + g * TABLE_STRIDE);
        dst[0] = make_float4(e[0], e[1], e[2],  e[3]);
        dst[1] = make_float4(e[4], e[5], e[6],  e[7]);
        dst[2] = make_float4(e[8], e[9], e[10], e[11]);
    }

    if (g >= N_STATIONS) return;
    float4 a = __ldg(reinterpret_cast<const float4*>(amps   + (size_t)g * 4));
    float4 p = __ldg(reinterpret_cast<const float4*>(phases + (size_t)g * 4));
    __half2 h[4];
    h[0] = __floats2half2_rn(a.x, a.y);
    h[1] = __floats2half2_rn(a.z, a.w);
    h[2] = __floats2half2_rn(p.x, p.y);
    h[3] = __floats2half2_rn(p.z, p.w);
    *reinterpret_cast<float4*>(g_pack + (size_t)g * 8) =
        *reinterpret_cast<const float4*>(h);
}

// ---------------------------------------------------------------------------
// Kernel B: smoothing — ONE thread/station, EIGHT 16B gathers (halved vs R4).
// Neighbor amp+phase arrive fp16 in a single record; __sincosf runs inline
// behind the gathers (hidden; proven in R8). Own-station contribution (0.8
// weight) uses exact fp32 amps/phases. Writes duplicated coefficient pairs.
// ---------------------------------------------------------------------------
__global__ void __launch_bounds__(256) smooth_kernel(
    const float* __restrict__ off,
    const float* __restrict__ trend,
    const float* __restrict__ amps,
    const float* __restrict__ phases,
    const int*   __restrict__ nidx,
    const float* __restrict__ nw)
{
    const int st = blockIdx.x * blockDim.x + threadIdx.x;
    if (st >= N_STATIONS) return;

    int4   ni0 = __ldg(reinterpret_cast<const int4*>(nidx + (size_t)st * K_NEIGH));
    int4   ni1 = __ldg(reinterpret_cast<const int4*>(nidx + (size_t)st * K_NEIGH) + 1);
    float4 w0  = __ldg(reinterpret_cast<const float4*>(nw + (size_t)st * K_NEIGH));
    float4 w1  = __ldg(reinterpret_cast<const float4*>(nw + (size_t)st * K_NEIGH) + 1);
    int   nbv[K_NEIGH] = {ni0.x, ni0.y, ni0.z, ni0.w, ni1.x, ni1.y, ni1.z, ni1.w};
    float wv [K_NEIGH] = {w0.x,  w0.y,  w0.z,  w0.w,  w1.x,  w1.y,  w1.z,  w1.w};

    // 8 independent 16B gathers, front-batched
    float4 gp[K_NEIGH];
#pragma unroll
    for (int k = 0; k < K_NEIGH; ++k)
        gp[k] = __ldg(reinterpret_cast<const float4*>(
                      reinterpret_cast<const char*>(g_pack) + (size_t)nbv[k] * 16));

    float aa[N_COMP] = {0.f, 0.f, 0.f, 0.f};
    float re[N_COMP] = {0.f, 0.f, 0.f, 0.f};
    float im[N_COMP] = {0.f, 0.f, 0.f, 0.f};
#pragma unroll
    for (int k = 0; k < K_NEIGH; ++k) {
        float w = wv[k];
        const __half2* h = reinterpret_cast<const __half2*>(&gp[k]);
        float2 a01 = __half22float2(h[0]);
        float2 a23 = __half22float2(h[1]);
        float2 p01 = __half22float2(h[2]);
        float2 p23 = __half22float2(h[3]);
        float av[4] = {a01.x, a01.y, a23.x, a23.y};
        float pv[4] = {p01.x, p01.y, p23.x, p23.y};
#pragma unroll
        for (int i = 0; i < N_COMP; ++i) {
            float sp, cp;
            __sincosf(pv[i], &sp, &cp);
            aa[i] = fmaf(w, av[i], aa[i]);
            re[i] = fmaf(w, cp, re[i]);
            im[i] = fmaf(w, sp, im[i]);
        }
    }

    float4 oa = __ldg(reinterpret_cast<const float4*>(amps   + (size_t)st * 4));
    float4 op = __ldg(reinterpret_cast<const float4*>(phases + (size_t)st * 4));
    float a0[4] = {oa.x, oa.y, oa.z, oa.w};
    float p0[4] = {op.x, op.y, op.z, op.w};

    float A[N_COMP], B[N_COMP];
#pragma unroll
    for (int i = 0; i < N_COMP; ++i) {
        float amp_s = KEEP_C * a0[i] + SMOOTH_C * aa[i];
        float sp, cp;
        __sincosf(p0[i], &sp, &cp);
        float mr = KEEP_C * cp + SMOOTH_C * re[i];
        float mi = KEEP_C * sp + SMOOTH_C * im[i];
        float inv = rsqrtf(fmaxf(mr * mr + mi * mi, 1e-30f));
        A[i] = amp_s * mr * inv;
        B[i] = amp_s * mi * inv;
    }

    float o  = __ldg(off + st);
    float tr = __ldg(trend + st);
    float4* dst = reinterpret_cast<float4*>(g_coeff + (size_t)st * COEFF_STRIDE);
    dst[0] = make_float4(o,    o,    tr,   tr);
    dst[1] = make_float4(A[0], A[0], A[1], A[1]);
    dst[2] = make_float4(A[2], A[2], A[3], A[3]);
    dst[3] = make_float4(B[0], B[0], B[1], B[1]);
    dst[4] = make_float4(B[2], B[2], B[3], B[3]);
}

// ---------------------------------------------------------------------------
// Kernel C: persistent evaluation (one full 4-CTA wave). Tile coefficients
// staged to smem once; broadcast LDS.128; table in regs; two FMA2 chains
// (depth 5 / 4) + 1 add2 = 10 ops per 4 outputs; streaming STG.128.
// ---------------------------------------------------------------------------
__global__ void __launch_bounds__(256, 4) eval_kernel(float* __restrict__ out)
{
    __shared__ float4 s_coeff[TILE * 5];   // 13520 B

    const int  col    = threadIdx.x;       // chunks 0..249 real
    const bool active = (col < CHUNKS);

    const int s_base = blockIdx.x * TILE;
    const int ns     = min(TILE, N_STATIONS - s_base);
    if (ns <= 0) return;

    {
        const float4* gsrc = reinterpret_cast<const float4*>(g_coeff) + (size_t)s_base * 5;
        const int total_f4 = ns * 5;
        for (int i = threadIdx.x; i < total_f4; i += 256)
            s_coeff[i] = gsrc[i];
    }

    u64 tt2[2];
    u64 ss2[2][4];
    u64 cc2[2][4];
    if (active) {
#pragma unroll
        for (int h = 0; h < 2; ++h) {
            const float* tpA = g_table + (col * 4 + 2 * h)     * TABLE_STRIDE;
            const float* tpB = g_table + (col * 4 + 2 * h + 1) * TABLE_STRIDE;
            float4 a0 = reinterpret_cast<const float4*>(tpA)[0];
            float4 a1 = reinterpret_cast<const float4*>(tpA)[1];
            float4 a2 = reinterpret_cast<const float4*>(tpA)[2];
            float4 b0 = reinterpret_cast<const float4*>(tpB)[0];
            float4 b1 = reinterpret_cast<const float4*>(tpB)[1];
            float4 b2 = reinterpret_cast<const float4*>(tpB)[2];
            tt2[h]    = pk2(a0.x, b0.x);
            ss2[h][0] = pk2(a0.y, b0.y);
            ss2[h][1] = pk2(a0.z, b0.z);
            ss2[h][2] = pk2(a0.w, b0.w);
            ss2[h][3] = pk2(a1.x, b1.x);
            cc2[h][0] = pk2(a1.y, b1.y);
            cc2[h][1] = pk2(a1.z, b1.z);
            cc2[h][2] = pk2(a1.w, b1.w);
            cc2[h][3] = pk2(a2.x, b2.x);
        }
    }

    __syncthreads();

    for (int j = 0; j < ns; ++j) {
        const ulonglong2* cp = reinterpret_cast<const ulonglong2*>(&s_coeff[j * 5]);
        ulonglong2 x0 = cp[0];  // {off,off},{trend,trend}
        ulonglong2 x1 = cp[1];  // {A0,A0},{A1,A1}
        ulonglong2 x2 = cp[2];  // {A2,A2},{A3,A3}
        ulonglong2 x3 = cp[3];  // {B0,B0},{B1,B1}
        ulonglong2 x4 = cp[4];  // {B2,B2},{B3,B3}

        if (active) {
            u64 r[2];
#pragma unroll
            for (int h = 0; h < 2; ++h) {
                u64 p0 = fma2(x0.y, tt2[h],    x0.x);    // off + trend*t
                u64 p1 = mul2(x3.x, cc2[h][0]);          // B0*c0
                p0 = fma2(x1.x, ss2[h][0], p0);          // +A0*s0
                p1 = fma2(x3.y, cc2[h][1], p1);          // +B1*c1
                p0 = fma2(x1.y, ss2[h][1], p0);          // +A1*s1
                p1 = fma2(x4.x, cc2[h][2], p1);          // +B2*c2
                p0 = fma2(x2.x, ss2[h][2], p0);          // +A2*s2
                p1 = fma2(x4.y, cc2[h][3], p1);          // +B3*c3
                p0 = fma2(x2.y, ss2[h][3], p0);          // +A3*s3
                r[h] = add2(p0, p1);
            }
            stcs2(out + (size_t)(s_base + j) * N_TIME + col * 4, r[0], r[1]);
        }
    }
}

// ---------------------------------------------------------------------------
extern "C" void kernel_launch(void* const* d_in, const int* in_sizes, int n_in,
                              void* d_out, int out_size)
{
    const float* time_vector = (const float*)d_in[0];
    const float* off         = (const float*)d_in[1];
    const float* trend       = (const float*)d_in[2];
    const float* amps        = (const float*)d_in[3];
    const float* phases      = (const float*)d_in[4];
    const int*   nidx        = (const int*)  d_in[5];
    const float* nw          = (const float*)d_in[6];
    const float* periods     = (const float*)d_in[7];
    float* out = (float*)d_out;

    pack_kernel  <<<(N_STATIONS + 255) / 256, 256>>>(amps, phases, time_vector, periods);
    smooth_kernel<<<(N_STATIONS + 255) / 256, 256>>>(off, trend, amps, phases, nidx, nw);
    eval_kernel  <<<GRID_EVAL, 256>>>(out);
}

// round 11
// speedup vs baseline: 1.1886x; 1.1029x over previous
#include <cuda_runtime.h>
#include <math.h>

#define N_STATIONS 100000
#define N_TIME     1000
#define K_NEIGH    8
#define SMOOTH_C   0.2f
#define KEEP_C     0.8f
#define N_COMP     4
#define CHUNKS     250    // 1000 times / 4 per thread
#define GRID_EVAL  592    // 148 SMs x 4 CTAs, one full wave
#define TILE       169    // stations per block (592*169 >= 100000)

typedef unsigned long long u64;

// ---- packed f32x2 helpers ---------------------------------------------------
__device__ __forceinline__ u64 pk2(float lo, float hi) {
    u64 r; asm("mov.b64 %0, {%1, %2};" : "=l"(r) : "f"(lo), "f"(hi)); return r;
}
__device__ __forceinline__ u64 fma2(u64 a, u64 b, u64 c) {
    u64 d; asm("fma.rn.f32x2 %0, %1, %2, %3;" : "=l"(d) : "l"(a), "l"(b), "l"(c)); return d;
}
__device__ __forceinline__ u64 mul2(u64 a, u64 b) {
    u64 d; asm("mul.rn.f32x2 %0, %1, %2;" : "=l"(d) : "l"(a), "l"(b)); return d;
}
__device__ __forceinline__ u64 add2(u64 a, u64 b) {
    u64 d; asm("add.rn.f32x2 %0, %1, %2;" : "=l"(d) : "l"(a), "l"(b)); return d;
}
__device__ __forceinline__ void stcs2(void* p, u64 a, u64 b) {
    asm volatile("st.global.cs.v2.u64 [%0], {%1, %2};" :: "l"(p), "l"(a), "l"(b) : "memory");
}

// ---------------------------------------------------------------------------
// SINGLE fused kernel: per-block smoothing (169 stations, 1 thread each,
// exact fp32, gathers front-batched) -> smem coefficients; per-thread time
// table computed in registers with accurate sincosf (no global tables, no
// extra kernels); one __syncthreads; then the converged eval loop:
// broadcast LDS.128 coefficients, two FMA2 chains + add2, streaming STG.128.
//   A_i = amp_s*cos(ph_s) (x sin(wt)),  B_i = amp_s*sin(ph_s) (x cos(wt)),
//   cos(atan2(im,re)) = re*rsqrt(re^2+im^2) -> no atan2.
// ---------------------------------------------------------------------------
__global__ void __launch_bounds__(256, 4) fused_kernel(
    float* __restrict__ out,
    const float* __restrict__ time_vector,
    const float* __restrict__ off,
    const float* __restrict__ trend,
    const float* __restrict__ amps,
    const float* __restrict__ phases,
    const int*   __restrict__ nidx,
    const float* __restrict__ nw,
    const float* __restrict__ periods)
{
    __shared__ float4 s_coeff[TILE * 5];   // 13520 B

    const int  tid    = threadIdx.x;
    const int  col    = tid;               // chunks 0..249 real
    const bool active = (col < CHUNKS);

    const int s_base = blockIdx.x * TILE;
    const int ns     = min(TILE, N_STATIONS - s_base);
    if (ns <= 0) return;

    // ---- Phase A: smoothing, one station per thread (threads 0..ns-1) -----
    if (tid < ns) {
        const int st = s_base + tid;

        int4   ni0 = __ldg(reinterpret_cast<const int4*>(nidx + (size_t)st * K_NEIGH));
        int4   ni1 = __ldg(reinterpret_cast<const int4*>(nidx + (size_t)st * K_NEIGH) + 1);
        float4 w0  = __ldg(reinterpret_cast<const float4*>(nw + (size_t)st * K_NEIGH));
        float4 w1  = __ldg(reinterpret_cast<const float4*>(nw + (size_t)st * K_NEIGH) + 1);
        int   nbv[K_NEIGH] = {ni0.x, ni0.y, ni0.z, ni0.w, ni1.x, ni1.y, ni1.z, ni1.w};
        float wv [K_NEIGH] = {w0.x,  w0.y,  w0.z,  w0.w,  w1.x,  w1.y,  w1.z,  w1.w};

        float aa[N_COMP] = {0.f, 0.f, 0.f, 0.f};
        float re[N_COMP] = {0.f, 0.f, 0.f, 0.f};
        float im[N_COMP] = {0.f, 0.f, 0.f, 0.f};

#pragma unroll
        for (int k = 0; k < K_NEIGH; ++k) {
            const size_t nb = (size_t)nbv[k];
            float4 na = __ldg(reinterpret_cast<const float4*>(amps   + nb * 4));
            float4 np = __ldg(reinterpret_cast<const float4*>(phases + nb * 4));
            float w = wv[k];
            float av[4] = {na.x, na.y, na.z, na.w};
            float pv[4] = {np.x, np.y, np.z, np.w};
#pragma unroll
            for (int i = 0; i < N_COMP; ++i) {
                float sp, cp;
                __sincosf(pv[i], &sp, &cp);
                aa[i] = fmaf(w, av[i], aa[i]);
                re[i] = fmaf(w, cp, re[i]);
                im[i] = fmaf(w, sp, im[i]);
            }
        }

        float4 oa = __ldg(reinterpret_cast<const float4*>(amps   + (size_t)st * 4));
        float4 op = __ldg(reinterpret_cast<const float4*>(phases + (size_t)st * 4));
        float a0[4] = {oa.x, oa.y, oa.z, oa.w};
        float p0[4] = {op.x, op.y, op.z, op.w};

        float A[N_COMP], B[N_COMP];
#pragma unroll
        for (int i = 0; i < N_COMP; ++i) {
            float amp_s = KEEP_C * a0[i] + SMOOTH_C * aa[i];
            float sp, cp;
            __sincosf(p0[i], &sp, &cp);
            float mr = KEEP_C * cp + SMOOTH_C * re[i];
            float mi = KEEP_C * sp + SMOOTH_C * im[i];
            float inv = rsqrtf(fmaxf(mr * mr + mi * mi, 1e-30f));
            A[i] = amp_s * mr * inv;
            B[i] = amp_s * mi * inv;
        }

        float o  = __ldg(off + st);
        float tr = __ldg(trend + st);
        float4* dst = &s_coeff[tid * 5];
        dst[0] = make_float4(o,    o,    tr,   tr);
        dst[1] = make_float4(A[0], A[0], A[1], A[1]);
        dst[2] = make_float4(A[2], A[2], A[3], A[3]);
        dst[3] = make_float4(B[0], B[0], B[1], B[1]);
        dst[4] = make_float4(B[2], B[2], B[3], B[3]);
    }

    // ---- Phase B: per-thread time table in registers (accurate sincosf) ----
    u64 tt2[2];
    u64 ss2[2][4];
    u64 cc2[2][4];
    if (active) {
        float4 tq = __ldg(reinterpret_cast<const float4*>(time_vector + col * 4));
        float tv[4] = {tq.x, tq.y, tq.z, tq.w};
        float wfr[4];
#pragma unroll
        for (int i = 0; i < N_COMP; ++i)
            wfr[i] = 6.2831853071795864769f / __ldg(periods + i);

        float sv[4][4], cv[4][4];   // [q][i]
#pragma unroll
        for (int q = 0; q < 4; ++q)
#pragma unroll
            for (int i = 0; i < N_COMP; ++i)
                sincosf(wfr[i] * tv[q], &sv[q][i], &cv[q][i]);

#pragma unroll
        for (int h = 0; h < 2; ++h) {
            tt2[h] = pk2(tv[2 * h], tv[2 * h + 1]);
#pragma unroll
            for (int i = 0; i < N_COMP; ++i) {
                ss2[h][i] = pk2(sv[2 * h][i], sv[2 * h + 1][i]);
                cc2[h][i] = pk2(cv[2 * h][i], cv[2 * h + 1][i]);
            }
        }
    }

    __syncthreads();

    // ---- Phase C: evaluation -------------------------------------------------
    for (int j = 0; j < ns; ++j) {
        const ulonglong2* cp = reinterpret_cast<const ulonglong2*>(&s_coeff[j * 5]);
        ulonglong2 x0 = cp[0];  // {off,off},{trend,trend}
        ulonglong2 x1 = cp[1];  // {A0,A0},{A1,A1}
        ulonglong2 x2 = cp[2];  // {A2,A2},{A3,A3}
        ulonglong2 x3 = cp[3];  // {B0,B0},{B1,B1}
        ulonglong2 x4 = cp[4];  // {B2,B2},{B3,B3}

        if (active) {
            u64 r[2];
#pragma unroll
            for (int h = 0; h < 2; ++h) {
                u64 p0 = fma2(x0.y, tt2[h],    x0.x);    // off + trend*t
                u64 p1 = mul2(x3.x, cc2[h][0]);          // B0*c0
                p0 = fma2(x1.x, ss2[h][0], p0);          // +A0*s0
                p1 = fma2(x3.y, cc2[h][1], p1);          // +B1*c1
                p0 = fma2(x1.y, ss2[h][1], p0);          // +A1*s1
                p1 = fma2(x4.x, cc2[h][2], p1);          // +B2*c2
                p0 = fma2(x2.x, ss2[h][2], p0);          // +A2*s2
                p1 = fma2(x4.y, cc2[h][3], p1);          // +B3*c3
                p0 = fma2(x2.y, ss2[h][3], p0);          // +A3*s3
                r[h] = add2(p0, p1);
            }
            stcs2(out + (size_t)(s_base + j) * N_TIME + col * 4, r[0], r[1]);
        }
    }
}

// ---------------------------------------------------------------------------
extern "C" void kernel_launch(void* const* d_in, const int* in_sizes, int n_in,
                              void* d_out, int out_size)
{
    const float* time_vector = (const float*)d_in[0];
    const float* off         = (const float*)d_in[1];
    const float* trend       = (const float*)d_in[2];
    const float* amps        = (const float*)d_in[3];
    const float* phases      = (const float*)d_in[4];
    const int*   nidx        = (const int*)  d_in[5];
    const float* nw          = (const float*)d_in[6];
    const float* periods     = (const float*)d_in[7];
    float* out = (float*)d_out;

    fused_kernel<<<GRID_EVAL, 256>>>(out, time_vector, off, trend, amps,
                                     phases, nidx, nw, periods);
}

// round 12
// speedup vs baseline: 1.2353x; 1.0393x over previous
#include <cuda_runtime.h>
#include <math.h>

#define N_STATIONS 100000
#define N_TIME     1000
#define K_NEIGH    8
#define SMOOTH_C   0.2f
#define KEEP_C     0.8f
#define N_COMP     4
#define CHUNKS     250    // 1000 times / 4 per thread
#define TILE       128    // stations per block (2 smoothing threads each)
#define GRID_EVAL  ((N_STATIONS + TILE - 1) / TILE)   // 782

typedef unsigned long long u64;

// ---- packed f32x2 helpers ---------------------------------------------------
__device__ __forceinline__ u64 pk2(float lo, float hi) {
    u64 r; asm("mov.b64 %0, {%1, %2};" : "=l"(r) : "f"(lo), "f"(hi)); return r;
}
__device__ __forceinline__ u64 fma2(u64 a, u64 b, u64 c) {
    u64 d; asm("fma.rn.f32x2 %0, %1, %2, %3;" : "=l"(d) : "l"(a), "l"(b), "l"(c)); return d;
}
__device__ __forceinline__ u64 mul2(u64 a, u64 b) {
    u64 d; asm("mul.rn.f32x2 %0, %1, %2;" : "=l"(d) : "l"(a), "l"(b)); return d;
}
__device__ __forceinline__ u64 add2(u64 a, u64 b) {
    u64 d; asm("add.rn.f32x2 %0, %1, %2;" : "=l"(d) : "l"(a), "l"(b)); return d;
}
__device__ __forceinline__ void stcs2(void* p, u64 a, u64 b) {
    asm volatile("st.global.cs.v2.u64 [%0], {%1, %2};" :: "l"(p), "l"(a), "l"(b) : "memory");
}

// ---------------------------------------------------------------------------
// SINGLE fused kernel.
// Phase A: smoothing with TWO threads per station (even lane: nbrs 0-3, odd:
//   4-7), exact fp32, shfl_xor(1) combine; each lane finalizes 2 of 4
//   components and writes duplicated pairs straight into smem.
// Phase B: per-thread time table in registers via accurate sincosf.
// Phase C: converged eval loop — broadcast LDS.128 coefficients, two FMA2
//   chains + add2, streaming STG.128.
//   A_i = amp_s*cos(ph_s) (x sin(wt)),  B_i = amp_s*sin(ph_s) (x cos(wt)),
//   cos(atan2(im,re)) = re*rsqrt(re^2+im^2) -> no atan2.
// ---------------------------------------------------------------------------
__global__ void __launch_bounds__(256, 4) fused_kernel(
    float* __restrict__ out,
    const float* __restrict__ time_vector,
    const float* __restrict__ off,
    const float* __restrict__ trend,
    const float* __restrict__ amps,
    const float* __restrict__ phases,
    const int*   __restrict__ nidx,
    const float* __restrict__ nw,
    const float* __restrict__ periods)
{
    __shared__ float4 s_coeff[TILE * 5];   // 10240 B

    const int  tid    = threadIdx.x;
    const int  col    = tid;               // chunks 0..249 real
    const bool active = (col < CHUNKS);

    const int s_base = blockIdx.x * TILE;
    const int ns     = min(TILE, N_STATIONS - s_base);
    if (ns <= 0) return;

    // ---- Phase A: smoothing, two threads per station -----------------------
    {
        const int lst  = tid >> 1;          // local station 0..127
        const int half = tid & 1;           // neighbor group
        if (lst < ns) {
            const int st = s_base + lst;

            int4   ni = __ldg(reinterpret_cast<const int4*>(nidx + (size_t)st * K_NEIGH) + half);
            float4 wf = __ldg(reinterpret_cast<const float4*>(nw   + (size_t)st * K_NEIGH) + half);
            int   nbv[4] = {ni.x, ni.y, ni.z, ni.w};
            float wv [4] = {wf.x, wf.y, wf.z, wf.w};

            float aa[N_COMP] = {0.f, 0.f, 0.f, 0.f};
            float re[N_COMP] = {0.f, 0.f, 0.f, 0.f};
            float im[N_COMP] = {0.f, 0.f, 0.f, 0.f};

#pragma unroll
            for (int k = 0; k < 4; ++k) {
                const size_t nb = (size_t)nbv[k];
                float4 na = __ldg(reinterpret_cast<const float4*>(amps   + nb * 4));
                float4 np = __ldg(reinterpret_cast<const float4*>(phases + nb * 4));
                float w = wv[k];
                float av[4] = {na.x, na.y, na.z, na.w};
                float pv[4] = {np.x, np.y, np.z, np.w};
#pragma unroll
                for (int i = 0; i < N_COMP; ++i) {
                    float sp, cp;
                    __sincosf(pv[i], &sp, &cp);
                    aa[i] = fmaf(w, av[i], aa[i]);
                    re[i] = fmaf(w, cp, re[i]);
                    im[i] = fmaf(w, sp, im[i]);
                }
            }

            // combine halves (lane pair within the same warp)
            const unsigned m = 0xFFFFFFFFu;
#pragma unroll
            for (int i = 0; i < N_COMP; ++i) {
                aa[i] += __shfl_xor_sync(m, aa[i], 1);
                re[i] += __shfl_xor_sync(m, re[i], 1);
                im[i] += __shfl_xor_sync(m, im[i], 1);
            }

            // this lane finalizes components c0, c0+1 (exact own-station phasor)
            const int c0 = half * 2;
            float2 oa = *reinterpret_cast<const float2*>(amps   + (size_t)st * 4 + c0);
            float2 op = *reinterpret_cast<const float2*>(phases + (size_t)st * 4 + c0);
            float a0[2] = {oa.x, oa.y};
            float p0[2] = {op.x, op.y};

            float A[2], B[2];
#pragma unroll
            for (int i = 0; i < 2; ++i) {
                float amp_s = KEEP_C * a0[i] + SMOOTH_C * aa[c0 + i];
                float sp, cp;
                __sincosf(p0[i], &sp, &cp);
                float mr = KEEP_C * cp + SMOOTH_C * re[c0 + i];
                float mi = KEEP_C * sp + SMOOTH_C * im[c0 + i];
                float inv = rsqrtf(fmaxf(mr * mr + mi * mi, 1e-30f));
                A[i] = amp_s * mr * inv;
                B[i] = amp_s * mi * inv;
            }

            float4* dst = &s_coeff[lst * 5];
            if (half == 0) {
                float o  = __ldg(off + st);
                float tr = __ldg(trend + st);
                dst[0] = make_float4(o,    o,    tr,   tr);
                dst[1] = make_float4(A[0], A[0], A[1], A[1]);   // A0, A1
                dst[3] = make_float4(B[0], B[0], B[1], B[1]);   // B0, B1
            } else {
                dst[2] = make_float4(A[0], A[0], A[1], A[1]);   // A2, A3
                dst[4] = make_float4(B[0], B[0], B[1], B[1]);   // B2, B3
            }
        }
    }

    // ---- Phase B: per-thread time table in registers (accurate sincosf) ----
    u64 tt2[2];
    u64 ss2[2][4];
    u64 cc2[2][4];
    if (active) {
        float4 tq = __ldg(reinterpret_cast<const float4*>(time_vector + col * 4));
        float tv[4] = {tq.x, tq.y, tq.z, tq.w};
        float wfr[4];
#pragma unroll
        for (int i = 0; i < N_COMP; ++i)
            wfr[i] = 6.2831853071795864769f / __ldg(periods + i);

        float sv[4][4], cv[4][4];   // [q][i]
#pragma unroll
        for (int q = 0; q < 4; ++q)
#pragma unroll
            for (int i = 0; i < N_COMP; ++i)
                sincosf(wfr[i] * tv[q], &sv[q][i], &cv[q][i]);

#pragma unroll
        for (int h = 0; h < 2; ++h) {
            tt2[h] = pk2(tv[2 * h], tv[2 * h + 1]);
#pragma unroll
            for (int i = 0; i < N_COMP; ++i) {
                ss2[h][i] = pk2(sv[2 * h][i], sv[2 * h + 1][i]);
                cc2[h][i] = pk2(cv[2 * h][i], cv[2 * h + 1][i]);
            }
        }
    }

    __syncthreads();

    // ---- Phase C: evaluation -------------------------------------------------
    for (int j = 0; j < ns; ++j) {
        const ulonglong2* cp = reinterpret_cast<const ulonglong2*>(&s_coeff[j * 5]);
        ulonglong2 x0 = cp[0];  // {off,off},{trend,trend}
        ulonglong2 x1 = cp[1];  // {A0,A0},{A1,A1}
        ulonglong2 x2 = cp[2];  // {A2,A2},{A3,A3}
        ulonglong2 x3 = cp[3];  // {B0,B0},{B1,B1}
        ulonglong2 x4 = cp[4];  // {B2,B2},{B3,B3}

        if (active) {
            u64 r[2];
#pragma unroll
            for (int h = 0; h < 2; ++h) {
                u64 p0 = fma2(x0.y, tt2[h],    x0.x);    // off + trend*t
                u64 p1 = mul2(x3.x, cc2[h][0]);          // B0*c0
                p0 = fma2(x1.x, ss2[h][0], p0);          // +A0*s0
                p1 = fma2(x3.y, cc2[h][1], p1);          // +B1*c1
                p0 = fma2(x1.y, ss2[h][1], p0);          // +A1*s1
                p1 = fma2(x4.x, cc2[h][2], p1);          // +B2*c2
                p0 = fma2(x2.x, ss2[h][2], p0);          // +A2*s2
                p1 = fma2(x4.y, cc2[h][3], p1);          // +B3*c3
                p0 = fma2(x2.y, ss2[h][3], p0);          // +A3*s3
                r[h] = add2(p0, p1);
            }
            stcs2(out + (size_t)(s_base + j) * N_TIME + col * 4, r[0], r[1]);
        }
    }
}

// ---------------------------------------------------------------------------
extern "C" void kernel_launch(void* const* d_in, const int* in_sizes, int n_in,
                              void* d_out, int out_size)
{
    const float* time_vector = (const float*)d_in[0];
    const float* off         = (const float*)d_in[1];
    const float* trend       = (const float*)d_in[2];
    const float* amps        = (const float*)d_in[3];
    const float* phases      = (const float*)d_in[4];
    const int*   nidx        = (const int*)  d_in[5];
    const float* nw          = (const float*)d_in[6];
    const float* periods     = (const float*)d_in[7];
    float* out = (float*)d_out;

    fused_kernel<<<GRID_EVAL, 256>>>(out, time_vector, off, trend, amps,
                                     phases, nidx, nw, periods);
}

// round 13
// speedup vs baseline: 1.2409x; 1.0046x over previous
#include <cuda_runtime.h>
#include <math.h>

#define N_STATIONS 100000
#define N_TIME     1000
#define K_NEIGH    8
#define SMOOTH_C   0.2f
#define KEEP_C     0.8f
#define N_COMP     4
#define CHUNKS     250    // 1000 times / 4 per thread
#define TILE       128    // stations per block (2 smoothing threads each)
#define GRID_EVAL  ((N_STATIONS + TILE - 1) / TILE)   // 782

typedef unsigned long long u64;

// ---- packed f32x2 helpers ---------------------------------------------------
__device__ __forceinline__ u64 pk2(float lo, float hi) {
    u64 r; asm("mov.b64 %0, {%1, %2};" : "=l"(r) : "f"(lo), "f"(hi)); return r;
}
__device__ __forceinline__ u64 fma2(u64 a, u64 b, u64 c) {
    u64 d; asm("fma.rn.f32x2 %0, %1, %2, %3;" : "=l"(d) : "l"(a), "l"(b), "l"(c)); return d;
}
__device__ __forceinline__ u64 mul2(u64 a, u64 b) {
    u64 d; asm("mul.rn.f32x2 %0, %1, %2;" : "=l"(d) : "l"(a), "l"(b)); return d;
}
__device__ __forceinline__ u64 add2(u64 a, u64 b) {
    u64 d; asm("add.rn.f32x2 %0, %1, %2;" : "=l"(d) : "l"(a), "l"(b)); return d;
}
__device__ __forceinline__ void stcs2(void* p, u64 a, u64 b) {
    asm volatile("st.global.cs.v2.u64 [%0], {%1, %2};" :: "l"(p), "l"(a), "l"(b) : "memory");
}

// ---------------------------------------------------------------------------
// SINGLE fused kernel.
// Phase A: smoothing with TWO threads per station (even lane: nbrs 0-3, odd:
//   4-7), exact fp32, shfl_xor(1) combine; each lane finalizes 2 of 4
//   components and writes duplicated pairs straight into smem.
// Phase B: per-thread time table in registers via FAST __sincosf (args <=
//   ~126 rad -> phase err ~7.5e-6 rad -> output rel_err ~1e-5, gate is 1e-3).
//   This was the exposed prologue cost when it used accurate sincosf.
// Phase C: converged eval loop — broadcast LDS.128 coefficients, two FMA2
//   chains + add2, streaming STG.128.
//   A_i = amp_s*cos(ph_s) (x sin(wt)),  B_i = amp_s*sin(ph_s) (x cos(wt)),
//   cos(atan2(im,re)) = re*rsqrt(re^2+im^2) -> no atan2.
// ---------------------------------------------------------------------------
__global__ void __launch_bounds__(256, 4) fused_kernel(
    float* __restrict__ out,
    const float* __restrict__ time_vector,
    const float* __restrict__ off,
    const float* __restrict__ trend,
    const float* __restrict__ amps,
    const float* __restrict__ phases,
    const int*   __restrict__ nidx,
    const float* __restrict__ nw,
    const float* __restrict__ periods)
{
    __shared__ float4 s_coeff[TILE * 5];   // 10240 B

    const int  tid    = threadIdx.x;
    const int  col    = tid;               // chunks 0..249 real
    const bool active = (col < CHUNKS);

    const int s_base = blockIdx.x * TILE;
    const int ns     = min(TILE, N_STATIONS - s_base);
    if (ns <= 0) return;

    // ---- Phase A: smoothing, two threads per station -----------------------
    {
        const int lst  = tid >> 1;          // local station 0..127
        const int half = tid & 1;           // neighbor group
        if (lst < ns) {
            const int st = s_base + lst;

            int4   ni = __ldg(reinterpret_cast<const int4*>(nidx + (size_t)st * K_NEIGH) + half);
            float4 wf = __ldg(reinterpret_cast<const float4*>(nw   + (size_t)st * K_NEIGH) + half);
            int   nbv[4] = {ni.x, ni.y, ni.z, ni.w};
            float wv [4] = {wf.x, wf.y, wf.z, wf.w};

            float aa[N_COMP] = {0.f, 0.f, 0.f, 0.f};
            float re[N_COMP] = {0.f, 0.f, 0.f, 0.f};
            float im[N_COMP] = {0.f, 0.f, 0.f, 0.f};

#pragma unroll
            for (int k = 0; k < 4; ++k) {
                const size_t nb = (size_t)nbv[k];
                float4 na = __ldg(reinterpret_cast<const float4*>(amps   + nb * 4));
                float4 np = __ldg(reinterpret_cast<const float4*>(phases + nb * 4));
                float w = wv[k];
                float av[4] = {na.x, na.y, na.z, na.w};
                float pv[4] = {np.x, np.y, np.z, np.w};
#pragma unroll
                for (int i = 0; i < N_COMP; ++i) {
                    float sp, cp;
                    __sincosf(pv[i], &sp, &cp);
                    aa[i] = fmaf(w, av[i], aa[i]);
                    re[i] = fmaf(w, cp, re[i]);
                    im[i] = fmaf(w, sp, im[i]);
                }
            }

            // combine halves (lane pair within the same warp)
            const unsigned m = 0xFFFFFFFFu;
#pragma unroll
            for (int i = 0; i < N_COMP; ++i) {
                aa[i] += __shfl_xor_sync(m, aa[i], 1);
                re[i] += __shfl_xor_sync(m, re[i], 1);
                im[i] += __shfl_xor_sync(m, im[i], 1);
            }

            // this lane finalizes components c0, c0+1 (exact own-station phasor)
            const int c0 = half * 2;
            float2 oa = *reinterpret_cast<const float2*>(amps   + (size_t)st * 4 + c0);
            float2 op = *reinterpret_cast<const float2*>(phases + (size_t)st * 4 + c0);
            float a0[2] = {oa.x, oa.y};
            float p0[2] = {op.x, op.y};

            float A[2], B[2];
#pragma unroll
            for (int i = 0; i < 2; ++i) {
                float amp_s = KEEP_C * a0[i] + SMOOTH_C * aa[c0 + i];
                float sp, cp;
                __sincosf(p0[i], &sp, &cp);
                float mr = KEEP_C * cp + SMOOTH_C * re[c0 + i];
                float mi = KEEP_C * sp + SMOOTH_C * im[c0 + i];
                float inv = rsqrtf(fmaxf(mr * mr + mi * mi, 1e-30f));
                A[i] = amp_s * mr * inv;
                B[i] = amp_s * mi * inv;
            }

            float4* dst = &s_coeff[lst * 5];
            if (half == 0) {
                float o  = __ldg(off + st);
                float tr = __ldg(trend + st);
                dst[0] = make_float4(o,    o,    tr,   tr);
                dst[1] = make_float4(A[0], A[0], A[1], A[1]);   // A0, A1
                dst[3] = make_float4(B[0], B[0], B[1], B[1]);   // B0, B1
            } else {
                dst[2] = make_float4(A[0], A[0], A[1], A[1]);   // A2, A3
                dst[4] = make_float4(B[0], B[0], B[1], B[1]);   // B2, B3
            }
        }
    }

    // ---- Phase B: per-thread time table in registers (fast __sincosf) ------
    u64 tt2[2];
    u64 ss2[2][4];
    u64 cc2[2][4];
    if (active) {
        float4 tq = __ldg(reinterpret_cast<const float4*>(time_vector + col * 4));
        float tv[4] = {tq.x, tq.y, tq.z, tq.w};
        float wfr[4];
#pragma unroll
        for (int i = 0; i < N_COMP; ++i)
            wfr[i] = 6.2831853071795864769f / __ldg(periods + i);

        float sv[4][4], cv[4][4];   // [q][i]
#pragma unroll
        for (int q = 0; q < 4; ++q)
#pragma unroll
            for (int i = 0; i < N_COMP; ++i)
                __sincosf(wfr[i] * tv[q], &sv[q][i], &cv[q][i]);

#pragma unroll
        for (int h = 0; h < 2; ++h) {
            tt2[h] = pk2(tv[2 * h], tv[2 * h + 1]);
#pragma unroll
            for (int i = 0; i < N_COMP; ++i) {
                ss2[h][i] = pk2(sv[2 * h][i], sv[2 * h + 1][i]);
                cc2[h][i] = pk2(cv[2 * h][i], cv[2 * h + 1][i]);
            }
        }
    }

    __syncthreads();

    // ---- Phase C: evaluation -------------------------------------------------
    for (int j = 0; j < ns; ++j) {
        const ulonglong2* cp = reinterpret_cast<const ulonglong2*>(&s_coeff[j * 5]);
        ulonglong2 x0 = cp[0];  // {off,off},{trend,trend}
        ulonglong2 x1 = cp[1];  // {A0,A0},{A1,A1}
        ulonglong2 x2 = cp[2];  // {A2,A2},{A3,A3}
        ulonglong2 x3 = cp[3];  // {B0,B0},{B1,B1}
        ulonglong2 x4 = cp[4];  // {B2,B2},{B3,B3}

        if (active) {
            u64 r[2];
#pragma unroll
            for (int h = 0; h < 2; ++h) {
                u64 p0 = fma2(x0.y, tt2[h],    x0.x);    // off + trend*t
                u64 p1 = mul2(x3.x, cc2[h][0]);          // B0*c0
                p0 = fma2(x1.x, ss2[h][0], p0);          // +A0*s0
                p1 = fma2(x3.y, cc2[h][1], p1);          // +B1*c1
                p0 = fma2(x1.y, ss2[h][1], p0);          // +A1*s1
                p1 = fma2(x4.x, cc2[h][2], p1);          // +B2*c2
                p0 = fma2(x2.x, ss2[h][2], p0);          // +A2*s2
                p1 = fma2(x4.y, cc2[h][3], p1);          // +B3*c3
                p0 = fma2(x2.y, ss2[h][3], p0);          // +A3*s3
                r[h] = add2(p0, p1);
            }
            stcs2(out + (size_t)(s_base + j) * N_TIME + col * 4, r[0], r[1]);
        }
    }
}

// ---------------------------------------------------------------------------
extern "C" void kernel_launch(void* const* d_in, const int* in_sizes, int n_in,
                              void* d_out, int out_size)
{
    const float* time_vector = (const float*)d_in[0];
    const float* off         = (const float*)d_in[1];
    const float* trend       = (const float*)d_in[2];
    const float* amps        = (const float*)d_in[3];
    const float* phases      = (const float*)d_in[4];
    const int*   nidx        = (const int*)  d_in[5];
    const float* nw          = (const float*)d_in[6];
    const float* periods     = (const float*)d_in[7];
    float* out = (float*)d_out;

    fused_kernel<<<GRID_EVAL, 256>>>(out, time_vector, off, trend, amps,
                                     phases, nidx, nw, periods);
}